// round 4
// baseline (speedup 1.0000x reference)
#include <cuda_runtime.h>
#include <cstdint>
#include <cstddef>

// Problem: y[n][o] = sum_r sum_m A[r][n][m] * (sum_f X[m][f] * W[r][o][f])
// R=8, N=4096, F=128.
//
// Plan (no tcgen05 — harness PTX targets compute_103, arch-accelerated
// instructions unavailable; use mma.sync tf32 on the legacy HMMA pipe):
//   stage1: Zt[r][o][m] = (W_r @ X^T), 3-term tf32 split for fp32 accuracy,
//           stored rna-rounded to tf32.
//   main:   partial[s][n][o] over 16 K-splits (r x k-half), 128x128 CTA tile,
//           cp.async 3-stage pipeline, m16n8k8 tf32 mma.
//   reduce: out = sum_s partial[s]  (deterministic).

#define RREL   8
#define NN     4096
#define FF     128
#define KSPLIT 16
#define KPER   2048
#define KC     32
#define STAGES 3
#define ITERS  (KPER / KC)        // 64

#define SA     36                 // main: floats per smem row (32 + 4 pad)
#define CHF    (128 * SA)         // floats per chunk buffer (4608)
#define S1S    68                 // stage1: floats per smem row (64 + 4 pad)
#define S1CHF  (128 * S1S)        // 8704

// Scratch (allocation is forbidden -> device globals)
__device__ float g_Zt[(size_t)RREL * FF * NN];          // [r][o][m] tf32-rounded, 16MB
__device__ float g_partial[(size_t)KSPLIT * NN * FF];   // [s][n][o], 32MB

// ---------------------------------------------------------------------------
__device__ __forceinline__ uint32_t smem_to_u32(const void* p) {
    uint32_t a;
    asm("{ .reg .u64 t; cvta.to.shared.u64 t, %1; cvt.u32.u64 %0, t; }"
        : "=r"(a) : "l"(p));
    return a;
}

__device__ __forceinline__ uint32_t tf32_rna(float f) {
    uint32_t o;
    asm("cvt.rna.tf32.f32 %0, %1;" : "=r"(o) : "f"(f));
    return o;
}

__device__ __forceinline__ void mma_tf32(float d[4], const uint32_t a[4], const uint32_t b[2]) {
    asm volatile(
        "mma.sync.aligned.m16n8k8.row.col.f32.tf32.tf32.f32 "
        "{%0,%1,%2,%3}, {%4,%5,%6,%7}, {%8,%9}, {%0,%1,%2,%3};"
        : "+f"(d[0]), "+f"(d[1]), "+f"(d[2]), "+f"(d[3])
        : "r"(a[0]), "r"(a[1]), "r"(a[2]), "r"(a[3]), "r"(b[0]), "r"(b[1]));
}

__device__ __forceinline__ void cp_async16(uint32_t smem_addr, const void* g) {
    asm volatile("cp.async.cg.shared.global [%0], [%1], 16;"
                 :: "r"(smem_addr), "l"(g) : "memory");
}
#define CP_COMMIT() asm volatile("cp.async.commit_group;" ::: "memory")
#define CP_WAIT(n)  asm volatile("cp.async.wait_group %0;" :: "n"(n) : "memory")

// ---------------------------------------------------------------------------
// Stage 1: g_Zt[r][o][m] = sum_f W[r][o][f] * X[m][f]
// CTA tile: 128 (o) x 128 (m), K = 128 in two chunks of 64.
// 3-term tf32 split: hi*hi + hi*lo + lo*hi.
// Grid (32 m-tiles, 8 r), 256 threads (8 warps, warp tile 64x32).
// ---------------------------------------------------------------------------
#define S1_SMEM (4 * S1CHF * 4)   // 139264 bytes

__global__ __launch_bounds__(256, 1)
void rgcn_stage1(const float* __restrict__ X, const float* __restrict__ W) {
    extern __shared__ float smem[];
    float* whi = smem;
    float* wlo = smem + S1CHF;
    float* xhi = smem + 2 * S1CHF;
    float* xlo = smem + 3 * S1CHF;

    int tid  = threadIdx.x;
    int wid  = tid >> 5;
    int lane = tid & 31;
    int gid  = lane >> 2;
    int tig  = lane & 3;
    int wm   = wid >> 2;          // 0..1 (o rows block of 64)
    int wn   = wid & 3;           // 0..3 (m cols block of 32)
    int m0   = blockIdx.x * 128;
    int r    = blockIdx.y;

    float acc[4][4][4];
    #pragma unroll
    for (int a = 0; a < 4; a++)
        #pragma unroll
        for (int b = 0; b < 4; b++)
            #pragma unroll
            for (int c = 0; c < 4; c++) acc[a][b][c] = 0.0f;

    for (int ch = 0; ch < 2; ch++) {
        __syncthreads();   // guard smem reuse
        // Load + hi/lo split (128 rows x 64 cols each matrix)
        #pragma unroll
        for (int v = tid; v < 2048; v += 256) {
            int row = v >> 4, seg = v & 15;
            int soff = row * S1S + seg * 4;

            float4 w = *(const float4*)(W + ((size_t)r * FF + row) * FF + ch * 64 + seg * 4);
            float4 hi, lo;
            hi.x = __uint_as_float(__float_as_uint(w.x) & 0xFFFFE000u); lo.x = w.x - hi.x;
            hi.y = __uint_as_float(__float_as_uint(w.y) & 0xFFFFE000u); lo.y = w.y - hi.y;
            hi.z = __uint_as_float(__float_as_uint(w.z) & 0xFFFFE000u); lo.z = w.z - hi.z;
            hi.w = __uint_as_float(__float_as_uint(w.w) & 0xFFFFE000u); lo.w = w.w - hi.w;
            lo.x = __uint_as_float(tf32_rna(lo.x)); lo.y = __uint_as_float(tf32_rna(lo.y));
            lo.z = __uint_as_float(tf32_rna(lo.z)); lo.w = __uint_as_float(tf32_rna(lo.w));
            *(float4*)(whi + soff) = hi;
            *(float4*)(wlo + soff) = lo;

            float4 x = *(const float4*)(X + (size_t)(m0 + row) * FF + ch * 64 + seg * 4);
            hi.x = __uint_as_float(__float_as_uint(x.x) & 0xFFFFE000u); lo.x = x.x - hi.x;
            hi.y = __uint_as_float(__float_as_uint(x.y) & 0xFFFFE000u); lo.y = x.y - hi.y;
            hi.z = __uint_as_float(__float_as_uint(x.z) & 0xFFFFE000u); lo.z = x.z - hi.z;
            hi.w = __uint_as_float(__float_as_uint(x.w) & 0xFFFFE000u); lo.w = x.w - hi.w;
            lo.x = __uint_as_float(tf32_rna(lo.x)); lo.y = __uint_as_float(tf32_rna(lo.y));
            lo.z = __uint_as_float(tf32_rna(lo.z)); lo.w = __uint_as_float(tf32_rna(lo.w));
            *(float4*)(xhi + soff) = hi;
            *(float4*)(xlo + soff) = lo;
        }
        __syncthreads();

        #pragma unroll
        for (int ks = 0; ks < 8; ks++) {
            int k = ks * 8 + tig;
            uint32_t ah[4][4], al[4][4], bh[4][2], bl[4][2];
            #pragma unroll
            for (int mt = 0; mt < 4; mt++) {
                int roff = (wm * 64 + mt * 16 + gid) * S1S + k;
                ah[mt][0] = __float_as_uint(whi[roff]);
                ah[mt][1] = __float_as_uint(whi[roff + 8 * S1S]);
                ah[mt][2] = __float_as_uint(whi[roff + 4]);
                ah[mt][3] = __float_as_uint(whi[roff + 8 * S1S + 4]);
                al[mt][0] = __float_as_uint(wlo[roff]);
                al[mt][1] = __float_as_uint(wlo[roff + 8 * S1S]);
                al[mt][2] = __float_as_uint(wlo[roff + 4]);
                al[mt][3] = __float_as_uint(wlo[roff + 8 * S1S + 4]);
            }
            #pragma unroll
            for (int nt = 0; nt < 4; nt++) {
                int roff = (wn * 32 + nt * 8 + gid) * S1S + k;
                bh[nt][0] = __float_as_uint(xhi[roff]);
                bh[nt][1] = __float_as_uint(xhi[roff + 4]);
                bl[nt][0] = __float_as_uint(xlo[roff]);
                bl[nt][1] = __float_as_uint(xlo[roff + 4]);
            }
            #pragma unroll
            for (int mt = 0; mt < 4; mt++)
                #pragma unroll
                for (int nt = 0; nt < 4; nt++) {
                    mma_tf32(acc[mt][nt], ah[mt], bh[nt]);
                    mma_tf32(acc[mt][nt], ah[mt], bl[nt]);
                    mma_tf32(acc[mt][nt], al[mt], bh[nt]);
                }
        }
    }

    // Epilogue: row = o, col = m. Round to nearest tf32 and store.
    #pragma unroll
    for (int mt = 0; mt < 4; mt++)
        #pragma unroll
        for (int nt = 0; nt < 4; nt++) {
            int o = wm * 64 + mt * 16 + gid;
            int m = m0 + wn * 32 + nt * 8 + tig * 2;
            float* dst = g_Zt + ((size_t)r * FF + o) * NN + m;
            uint2 v0 = make_uint2(tf32_rna(acc[mt][nt][0]), tf32_rna(acc[mt][nt][1]));
            uint2 v1 = make_uint2(tf32_rna(acc[mt][nt][2]), tf32_rna(acc[mt][nt][3]));
            *(uint2*)dst = v0;
            *(uint2*)(dst + 8 * NN) = v1;
        }
}

// ---------------------------------------------------------------------------
// Main GEMM: partial[s][n][o] = sum_{k in slice} A[r][n][k] * Zt[r][o][k]
// Grid (32 n-tiles, 16 k-splits), 256 threads, 3-stage cp.async pipeline.
// 2 CTAs per SM (smem 110592 x2 fits 228KB).
// ---------------------------------------------------------------------------
#define MG_SMEM (2 * STAGES * CHF * 4)   // 110592 bytes

__global__ __launch_bounds__(256, 2)
void rgcn_main(const float* __restrict__ A) {
    extern __shared__ float smem[];
    float* As = smem;                    // STAGES chunk buffers
    float* Zs = smem + STAGES * CHF;
    uint32_t a_sb = smem_to_u32(As);
    uint32_t z_sb = smem_to_u32(Zs);

    int tid  = threadIdx.x;
    int wid  = tid >> 5;
    int lane = tid & 31;
    int gid  = lane >> 2;
    int tig  = lane & 3;
    int wm   = wid >> 2;                 // 0..1: n-rows block of 64
    int wn   = wid & 3;                  // 0..3: o-cols block of 32
    int n0   = blockIdx.x * 128;
    int sidx = blockIdx.y;
    int r    = sidx >> 1;
    int k0   = (sidx & 1) * KPER;

    const float* Abase = A + ((size_t)r * NN + n0) * NN + k0;
    const float* Zbase = g_Zt + (size_t)r * FF * NN + k0;

    float acc[4][4][4];
    #pragma unroll
    for (int a = 0; a < 4; a++)
        #pragma unroll
        for (int b = 0; b < 4; b++)
            #pragma unroll
            for (int c = 0; c < 4; c++) acc[a][b][c] = 0.0f;

    // Prologue: chunks 0..STAGES-2
    #pragma unroll
    for (int c = 0; c < STAGES - 1; c++) {
        #pragma unroll
        for (int v = tid; v < 1024; v += 256) {
            int row = v >> 3, seg = v & 7;
            uint32_t off = (uint32_t)(c * CHF + row * SA + seg * 4) * 4;
            const float* gp = Abase + c * KC + (size_t)row * NN + seg * 4;
            cp_async16(a_sb + off, gp);
            cp_async16(z_sb + off, Zbase + c * KC + (size_t)row * NN + seg * 4);
        }
        CP_COMMIT();
    }

    for (int i = 0; i < ITERS; i++) {
        CP_WAIT(STAGES - 2);
        __syncthreads();

        // Prefetch chunk i+STAGES-1 (overwrites buffer consumed at i-1; safe
        // because the syncthreads above proves everyone finished it).
        int j = i + STAGES - 1;
        if (j < ITERS) {
            int buf = j % STAGES;
            #pragma unroll
            for (int v = tid; v < 1024; v += 256) {
                int row = v >> 3, seg = v & 7;
                uint32_t off = (uint32_t)(buf * CHF + row * SA + seg * 4) * 4;
                cp_async16(a_sb + off, Abase + j * KC + (size_t)row * NN + seg * 4);
                cp_async16(z_sb + off, Zbase + j * KC + (size_t)row * NN + seg * 4);
            }
        }
        CP_COMMIT();

        // Compute chunk i
        const float* Ab = As + (i % STAGES) * CHF;
        const float* Zb = Zs + (i % STAGES) * CHF;
        #pragma unroll
        for (int ks = 0; ks < 4; ks++) {
            int k = ks * 8 + tig;
            uint32_t af[4][4], bf[4][2];
            #pragma unroll
            for (int mt = 0; mt < 4; mt++) {
                const float* p = Ab + (wm * 64 + mt * 16 + gid) * SA + k;
                af[mt][0] = tf32_rna(p[0]);
                af[mt][1] = tf32_rna(p[8 * SA]);
                af[mt][2] = tf32_rna(p[4]);
                af[mt][3] = tf32_rna(p[8 * SA + 4]);
            }
            #pragma unroll
            for (int nt = 0; nt < 4; nt++) {
                const float* p = Zb + (wn * 32 + nt * 8 + gid) * SA + k;
                bf[nt][0] = __float_as_uint(p[0]);   // Zt already tf32-rounded
                bf[nt][1] = __float_as_uint(p[4]);
            }
            #pragma unroll
            for (int mt = 0; mt < 4; mt++)
                #pragma unroll
                for (int nt = 0; nt < 4; nt++)
                    mma_tf32(acc[mt][nt], af[mt], bf[nt]);
        }
    }

    // Epilogue: row = n, col = o.
    #pragma unroll
    for (int mt = 0; mt < 4; mt++)
        #pragma unroll
        for (int nt = 0; nt < 4; nt++) {
            int n = n0 + wm * 64 + mt * 16 + gid;
            int o = wn * 32 + nt * 8 + tig * 2;
            float* dst = g_partial + ((size_t)sidx * NN + n) * FF + o;
            *(float2*)dst = make_float2(acc[mt][nt][0], acc[mt][nt][1]);
            *(float2*)(dst + 8 * FF) = make_float2(acc[mt][nt][2], acc[mt][nt][3]);
        }
}

// ---------------------------------------------------------------------------
// Reduce: out[n][o] = sum_s partial[s][n][o]   (deterministic)
// ---------------------------------------------------------------------------
__global__ __launch_bounds__(256)
void rgcn_reduce(float* __restrict__ out) {
    int idx = blockIdx.x * 256 + threadIdx.x;          // float4 index
    const float4* p = (const float4*)g_partial;
    const int stride = NN * FF / 4;
    float4 acc = p[idx];
    #pragma unroll
    for (int s = 1; s < KSPLIT; s++) {
        float4 t = p[(size_t)s * stride + idx];
        acc.x += t.x; acc.y += t.y; acc.z += t.z; acc.w += t.w;
    }
    ((float4*)out)[idx] = acc;
}

// ---------------------------------------------------------------------------
extern "C" void kernel_launch(void* const* d_in, const int* in_sizes, int n_in,
                              void* d_out, int out_size) {
    const float* A = (const float*)d_in[0];   // [8, 4096, 4096]
    const float* X = (const float*)d_in[1];   // [4096, 128]
    const float* W = (const float*)d_in[2];   // [8, 128, 128]
    float* out = (float*)d_out;               // [4096, 128]

    cudaFuncSetAttribute(rgcn_stage1, cudaFuncAttributeMaxDynamicSharedMemorySize, S1_SMEM);
    cudaFuncSetAttribute(rgcn_main,   cudaFuncAttributeMaxDynamicSharedMemorySize, MG_SMEM);

    rgcn_stage1<<<dim3(NN / 128, RREL), 256, S1_SMEM>>>(X, W);
    rgcn_main<<<dim3(NN / 128, KSPLIT), 256, MG_SMEM>>>(A);
    rgcn_reduce<<<(NN * FF / 4) / 256, 256>>>(out);
}

// round 7
// speedup vs baseline: 1.3364x; 1.3364x over previous
#include <cuda_runtime.h>
#include <cuda_fp16.h>
#include <cstdint>
#include <cstddef>

// y[n][o] = sum_r sum_m A[r][n][m] * Zt[r][o][m],  Zt = W_r @ X^T
// R=8, N=4096, F=128.
//
// stage1 (tf32 mma): Zt -> g_Zh as fp16, chunk-contiguous [r][ch][o][kc].
// main  (fp16 m16n8k16): partial[r][n][o], 128x128 CTA tile, K=4096,
//        A converted fp32->fp16 in-flight, ldmatrix fragments.
// reduce: out = sum_r partial[r].

#define RREL 8
#define NN   4096
#define FF   128
#define KC   32
#define NCH  (NN / KC)        // 128 chunks per relation
#define STG  4
#define ROWH 40               // halves per smem row (32 + 8 pad) = 80B, 16B-aligned

// stage1 constants
#define S1S  68               // floats per smem row (64 + 4 pad)
#define S1CHF (128 * S1S)

// Scratch (allocation forbidden -> device globals)
__device__ __half g_Zh[(size_t)RREL * NCH * FF * KC];     // 8MB fp16, chunk-contig
__device__ float  g_partial[(size_t)RREL * NN * FF];      // 16MB

// ---------------------------------------------------------------------------
__device__ __forceinline__ uint32_t smem_to_u32(const void* p) {
    uint32_t a;
    asm("{ .reg .u64 t; cvta.to.shared.u64 t, %1; cvt.u32.u64 %0, t; }"
        : "=r"(a) : "l"(p));
    return a;
}

__device__ __forceinline__ uint32_t tf32_rna(float f) {
    uint32_t o;
    asm("cvt.rna.tf32.f32 %0, %1;" : "=r"(o) : "f"(f));
    return o;
}

// pack two fp32 into one fp16x2 register (lo = a, hi = b)
__device__ __forceinline__ uint32_t f16x2_rn(float a, float b) {
    uint32_t o;
    asm("cvt.rn.f16x2.f32 %0, %2, %1;" : "=r"(o) : "f"(a), "f"(b));
    return o;
}

__device__ __forceinline__ void mma_tf32(float d[4], const uint32_t a[4], const uint32_t b[2]) {
    asm volatile(
        "mma.sync.aligned.m16n8k8.row.col.f32.tf32.tf32.f32 "
        "{%0,%1,%2,%3}, {%4,%5,%6,%7}, {%8,%9}, {%0,%1,%2,%3};"
        : "+f"(d[0]), "+f"(d[1]), "+f"(d[2]), "+f"(d[3])
        : "r"(a[0]), "r"(a[1]), "r"(a[2]), "r"(a[3]), "r"(b[0]), "r"(b[1]));
}

__device__ __forceinline__ void mma_f16(float d[4], const uint32_t a[4], const uint32_t b[2]) {
    asm volatile(
        "mma.sync.aligned.m16n8k16.row.col.f32.f16.f16.f32 "
        "{%0,%1,%2,%3}, {%4,%5,%6,%7}, {%8,%9}, {%0,%1,%2,%3};"
        : "+f"(d[0]), "+f"(d[1]), "+f"(d[2]), "+f"(d[3])
        : "r"(a[0]), "r"(a[1]), "r"(a[2]), "r"(a[3]), "r"(b[0]), "r"(b[1]));
}

__device__ __forceinline__ void ldmatrix_x4(uint32_t r[4], uint32_t addr) {
    asm volatile("ldmatrix.sync.aligned.m8n8.x4.shared.b16 {%0,%1,%2,%3}, [%4];"
                 : "=r"(r[0]), "=r"(r[1]), "=r"(r[2]), "=r"(r[3]) : "r"(addr));
}

__device__ __forceinline__ void cp_async16(uint32_t smem_addr, const void* g) {
    asm volatile("cp.async.cg.shared.global [%0], [%1], 16;"
                 :: "r"(smem_addr), "l"(g) : "memory");
}
#define CP_COMMIT() asm volatile("cp.async.commit_group;" ::: "memory")
#define CP_WAIT(n)  asm volatile("cp.async.wait_group %0;" :: "n"(n) : "memory")

// ---------------------------------------------------------------------------
// Stage 1: g_Zh[r][m>>5][o][m&31] = fp16( sum_f W[r][o][f] * X[m][f] )
// Single-pass tf32 (Z is fp16-quantized downstream; tf32 error 1.2e-4 ok).
// Grid (32 m-tiles, 8 r), 256 threads, warp tile 64(o) x 32(m).
// ---------------------------------------------------------------------------
#define S1_SMEM (2 * S1CHF * 4)   // 69632 bytes

__global__ __launch_bounds__(256, 1)
void rgcn_stage1(const float* __restrict__ X, const float* __restrict__ W) {
    extern __shared__ float smem[];
    float* ws = smem;
    float* xs = smem + S1CHF;

    int tid  = threadIdx.x;
    int wid  = tid >> 5;
    int lane = tid & 31;
    int gid  = lane >> 2;
    int tig  = lane & 3;
    int wm   = wid >> 2;          // 0..1 (o block of 64)
    int wn   = wid & 3;           // 0..3 (m block of 32)
    int m0   = blockIdx.x * 128;
    int r    = blockIdx.y;

    float acc[4][4][4];
    #pragma unroll
    for (int a = 0; a < 4; a++)
        #pragma unroll
        for (int b = 0; b < 4; b++)
            #pragma unroll
            for (int c = 0; c < 4; c++) acc[a][b][c] = 0.0f;

    for (int ch = 0; ch < 2; ch++) {
        __syncthreads();
        #pragma unroll
        for (int v = tid; v < 2048; v += 256) {
            int row = v >> 4, seg = v & 15;
            int soff = row * S1S + seg * 4;
            float4 w = *(const float4*)(W + ((size_t)r * FF + row) * FF + ch * 64 + seg * 4);
            w.x = __uint_as_float(tf32_rna(w.x)); w.y = __uint_as_float(tf32_rna(w.y));
            w.z = __uint_as_float(tf32_rna(w.z)); w.w = __uint_as_float(tf32_rna(w.w));
            *(float4*)(ws + soff) = w;
            float4 x = *(const float4*)(X + (size_t)(m0 + row) * FF + ch * 64 + seg * 4);
            x.x = __uint_as_float(tf32_rna(x.x)); x.y = __uint_as_float(tf32_rna(x.y));
            x.z = __uint_as_float(tf32_rna(x.z)); x.w = __uint_as_float(tf32_rna(x.w));
            *(float4*)(xs + soff) = x;
        }
        __syncthreads();

        #pragma unroll
        for (int ks = 0; ks < 8; ks++) {
            int k = ks * 8 + tig;
            uint32_t af[4][4], bf[4][2];
            #pragma unroll
            for (int mt = 0; mt < 4; mt++) {
                int roff = (wm * 64 + mt * 16 + gid) * S1S + k;
                af[mt][0] = __float_as_uint(ws[roff]);
                af[mt][1] = __float_as_uint(ws[roff + 8 * S1S]);
                af[mt][2] = __float_as_uint(ws[roff + 4]);
                af[mt][3] = __float_as_uint(ws[roff + 8 * S1S + 4]);
            }
            #pragma unroll
            for (int nt = 0; nt < 4; nt++) {
                int roff = (wn * 32 + nt * 8 + gid) * S1S + k;
                bf[nt][0] = __float_as_uint(xs[roff]);
                bf[nt][1] = __float_as_uint(xs[roff + 4]);
            }
            #pragma unroll
            for (int mt = 0; mt < 4; mt++)
                #pragma unroll
                for (int nt = 0; nt < 4; nt++)
                    mma_tf32(acc[mt][nt], af[mt], bf[nt]);
        }
    }

    // Epilogue: row = o, col = m. fp16, chunk-contiguous layout.
    #pragma unroll
    for (int mt = 0; mt < 4; mt++)
        #pragma unroll
        for (int nt = 0; nt < 4; nt++) {
            int o = wm * 64 + mt * 16 + gid;
            int m = m0 + wn * 32 + nt * 8 + tig * 2;
            int ch = m >> 5, kc = m & 31;
            uint32_t* dst = (uint32_t*)(g_Zh + (((size_t)r * NCH + ch) * FF + o) * KC + kc);
            *dst = f16x2_rn(acc[mt][nt][0], acc[mt][nt][1]);
            uint32_t* dst2 = (uint32_t*)(g_Zh + (((size_t)r * NCH + ch) * FF + o + 8) * KC + kc);
            *dst2 = f16x2_rn(acc[mt][nt][2], acc[mt][nt][3]);
        }
}

// ---------------------------------------------------------------------------
// Main GEMM: partial[r][n][o] = sum_k A[r][n][k] * Zh[r][o-chunks][k]
// Grid (32 n-tiles, 8 r), 512 threads (16 warps, warp tile 32n x 32o),
// fp16 m16n8k16, A converted in-flight, 4-stage pipeline.
// ---------------------------------------------------------------------------
#define MG_SMEM (2 * STG * 128 * ROWH * 2)   // 81920 bytes (A halves + Z halves)

__global__ __launch_bounds__(512, 1)
void rgcn_main(const float* __restrict__ A) {
    extern __shared__ __half hsm[];
    __half* As = hsm;                         // [STG][128][ROWH]
    __half* Zs = hsm + STG * 128 * ROWH;
    uint32_t as_u = smem_to_u32(As);
    uint32_t zs_u = smem_to_u32(Zs);

    int tid  = threadIdx.x;
    int lane = tid & 31;
    int wid  = tid >> 5;
    int gid  = lane >> 2;
    int tig  = lane & 3;
    int wn   = wid & 3;                       // n block of 32
    int wo   = wid >> 2;                      // o block of 32
    int n0   = blockIdx.x * 128;
    int r    = blockIdx.y;

    const float*  Ab = A + ((size_t)r * NN + n0) * NN;
    const __half* Zb = g_Zh + (size_t)r * NCH * FF * KC;

    // Producer mapping: thread -> (row, 8-float segment) of the A chunk
    int prow = tid >> 2, pseg = tid & 3;
    const float* ag = Ab + (size_t)prow * NN + pseg * 8;
    uint32_t a_sts = as_u + (uint32_t)(prow * ROWH + pseg * 8) * 2;   // bytes
    // Z cp.async mapping: thread -> 16B of the 8KB chunk
    const __half* zg = Zb + (size_t)prow * KC + pseg * 8;
    uint32_t z_sts = zs_u + (uint32_t)(prow * ROWH + pseg * 8) * 2;

    // ldmatrix per-lane base offsets (bytes within a stage)
    uint32_t a_lm = as_u + (uint32_t)((wn * 32 + (lane & 15)) * ROWH + (lane >> 4) * 8) * 2;
    uint32_t b_lm = zs_u + (uint32_t)((wo * 32 + ((lane >> 4) * 8 + (lane & 7))) * ROWH
                                      + ((lane >> 3) & 1) * 8) * 2;
    const uint32_t STAGE_B = 128 * ROWH * 2;  // bytes per stage

    float acc[2][4][4];
    #pragma unroll
    for (int a = 0; a < 2; a++)
        #pragma unroll
        for (int b = 0; b < 4; b++)
            #pragma unroll
            for (int c = 0; c < 4; c++) acc[a][b][c] = 0.0f;

    // Prologue: A regs for chunks 0,1; Z cp.async for chunks 0,1,2
    float4 f0a = *(const float4*)(ag);
    float4 f0b = *(const float4*)(ag + 4);
    float4 f1a = *(const float4*)(ag + KC);
    float4 f1b = *(const float4*)(ag + KC + 4);
    #pragma unroll
    for (int c = 0; c < 3; c++) {
        cp_async16(z_sts + c * STAGE_B, zg + (size_t)c * FF * KC);
        CP_COMMIT();
    }

    for (int i = 0; i < NCH; i++) {
        // STS A chunk i (fp32 -> fp16) into stage i%4
        {
            uint32_t h0 = f16x2_rn(f0a.x, f0a.y);
            uint32_t h1 = f16x2_rn(f0a.z, f0a.w);
            uint32_t h2 = f16x2_rn(f0b.x, f0b.y);
            uint32_t h3 = f16x2_rn(f0b.z, f0b.w);
            asm volatile("st.shared.v4.b32 [%0], {%1,%2,%3,%4};"
                         :: "r"(a_sts + (i & 3) * STAGE_B),
                            "r"(h0), "r"(h1), "r"(h2), "r"(h3) : "memory");
        }
        // shift pipeline, prefetch A chunk i+2
        f0a = f1a; f0b = f1b;
        if (i + 2 < NCH) {
            f1a = *(const float4*)(ag + (size_t)(i + 2) * KC);
            f1b = *(const float4*)(ag + (size_t)(i + 2) * KC + 4);
        }

        CP_WAIT(2);          // Z chunk i arrived
        __syncthreads();     // A STS visible; stage reuse safe

        // prefetch Z chunk i+3 into stage (i+3)%4
        if (i + 3 < NCH)
            cp_async16(z_sts + ((i + 3) & 3) * STAGE_B, zg + (size_t)(i + 3) * FF * KC);
        CP_COMMIT();

        // Compute chunk i
        uint32_t abase = a_lm + (i & 3) * STAGE_B;
        uint32_t bbase = b_lm + (i & 3) * STAGE_B;
        #pragma unroll
        for (int ks = 0; ks < 2; ks++) {
            uint32_t af[2][4], bf[4][2];
            #pragma unroll
            for (int mt = 0; mt < 2; mt++)
                ldmatrix_x4(af[mt], abase + (uint32_t)(mt * 16 * ROWH + ks * 16) * 2);
            #pragma unroll
            for (int p = 0; p < 2; p++) {
                uint32_t br[4];
                ldmatrix_x4(br, bbase + (uint32_t)(p * 16 * ROWH + ks * 16) * 2);
                bf[2 * p][0] = br[0]; bf[2 * p][1] = br[1];
                bf[2 * p + 1][0] = br[2]; bf[2 * p + 1][1] = br[3];
            }
            #pragma unroll
            for (int mt = 0; mt < 2; mt++)
                #pragma unroll
                for (int ob = 0; ob < 4; ob++)
                    mma_f16(acc[mt][ob], af[mt], bf[ob]);
        }
    }

    // Epilogue: rows n, cols o
    #pragma unroll
    for (int mt = 0; mt < 2; mt++)
        #pragma unroll
        for (int ob = 0; ob < 4; ob++) {
            int n = n0 + wn * 32 + mt * 16 + gid;
            int o = wo * 32 + ob * 8 + tig * 2;
            float* dst = g_partial + ((size_t)r * NN + n) * FF + o;
            *(float2*)dst = make_float2(acc[mt][ob][0], acc[mt][ob][1]);
            *(float2*)(dst + 8 * FF) = make_float2(acc[mt][ob][2], acc[mt][ob][3]);
        }
}

// ---------------------------------------------------------------------------
// Reduce: out[n][o] = sum_r partial[r][n][o]
// ---------------------------------------------------------------------------
__global__ __launch_bounds__(256)
void rgcn_reduce(float* __restrict__ out) {
    int idx = blockIdx.x * 256 + threadIdx.x;          // float4 index (131072)
    const float4* p = (const float4*)g_partial;
    const int stride = NN * FF / 4;
    float4 acc = p[idx];
    #pragma unroll
    for (int s = 1; s < RREL; s++) {
        float4 t = p[(size_t)s * stride + idx];
        acc.x += t.x; acc.y += t.y; acc.z += t.z; acc.w += t.w;
    }
    ((float4*)out)[idx] = acc;
}

// ---------------------------------------------------------------------------
extern "C" void kernel_launch(void* const* d_in, const int* in_sizes, int n_in,
                              void* d_out, int out_size) {
    const float* A = (const float*)d_in[0];   // [8, 4096, 4096]
    const float* X = (const float*)d_in[1];   // [4096, 128]
    const float* W = (const float*)d_in[2];   // [8, 128, 128]
    float* out = (float*)d_out;               // [4096, 128]

    cudaFuncSetAttribute(rgcn_stage1, cudaFuncAttributeMaxDynamicSharedMemorySize, S1_SMEM);
    cudaFuncSetAttribute(rgcn_main,   cudaFuncAttributeMaxDynamicSharedMemorySize, MG_SMEM);

    rgcn_stage1<<<dim3(NN / 128, RREL), 256, S1_SMEM>>>(X, W);
    rgcn_main<<<dim3(NN / 128, RREL), 512, MG_SMEM>>>(A);
    rgcn_reduce<<<(NN * FF / 4) / 256, 256>>>(out);
}